// round 13
// baseline (speedup 1.0000x reference)
#include <cuda_runtime.h>
#include <cuda_bf16.h>
#include <cstdint>
#include <math.h>

// Problem constants
#define B_  2
#define S_  2048
#define E_  1024
#define H_  16
#define D_  64
#define NT  (B_*S_)      // 4096 tokens
#define F3  (3*E_)       // 3072 qkv features

// ---------------------------------------------------------------------------
// Device-global scratch (no allocation allowed)
// ---------------------------------------------------------------------------
#define QKV_ELEMS ((size_t)B_*H_*S_*D_)
__device__ __nv_bfloat16 g_qhi[QKV_ELEMS], g_qlo[QKV_ELEMS];
__device__ __nv_bfloat16 g_khi[QKV_ELEMS], g_klo[QKV_ELEMS];
__device__ __nv_bfloat16 g_vhi[QKV_ELEMS], g_vlo[QKV_ELEMS];

__device__ __nv_bfloat16 g_xhi[(size_t)NT*E_],  g_xlo[(size_t)NT*E_];
__device__ __nv_bfloat16 g_wqhi[(size_t)F3*E_], g_wqlo[(size_t)F3*E_];
__device__ __nv_bfloat16 g_wohi[(size_t)E_*E_], g_wolo[(size_t)E_*E_];
__device__ __nv_bfloat16 g_ohi[(size_t)NT*E_],  g_olo[(size_t)NT*E_];

// ---------------------------------------------------------------------------
// Warp-level tensor-core helpers (portable PTX: sm_80+, assembles on sm_103)
// ---------------------------------------------------------------------------
__device__ __forceinline__ uint32_t smem_to_u32(const void* p) {
    uint32_t a;
    asm("{ .reg .u64 t; cvta.to.shared.u64 t, %1; cvt.u32.u64 %0, t; }"
        : "=r"(a) : "l"(p));
    return a;
}

__device__ __forceinline__ void ldsm_x4(uint32_t& r0, uint32_t& r1,
                                        uint32_t& r2, uint32_t& r3,
                                        uint32_t addr) {
    asm volatile("ldmatrix.sync.aligned.m8n8.x4.shared.b16 {%0,%1,%2,%3}, [%4];"
        : "=r"(r0), "=r"(r1), "=r"(r2), "=r"(r3) : "r"(addr));
}
__device__ __forceinline__ void ldsm_x4_trans(uint32_t& r0, uint32_t& r1,
                                              uint32_t& r2, uint32_t& r3,
                                              uint32_t addr) {
    asm volatile("ldmatrix.sync.aligned.m8n8.x4.trans.shared.b16 {%0,%1,%2,%3}, [%4];"
        : "=r"(r0), "=r"(r1), "=r"(r2), "=r"(r3) : "r"(addr));
}

__device__ __forceinline__ void mma_bf16(float c[4],
                                         uint32_t a0, uint32_t a1,
                                         uint32_t a2, uint32_t a3,
                                         uint32_t b0, uint32_t b1) {
    asm volatile(
        "mma.sync.aligned.m16n8k16.row.col.f32.bf16.bf16.f32 "
        "{%0,%1,%2,%3}, {%4,%5,%6,%7}, {%8,%9}, {%0,%1,%2,%3};"
        : "+f"(c[0]), "+f"(c[1]), "+f"(c[2]), "+f"(c[3])
        : "r"(a0), "r"(a1), "r"(a2), "r"(a3), "r"(b0), "r"(b1));
}

__device__ __forceinline__ void cp16(uint32_t dst, const void* src) {
    asm volatile("cp.async.cg.shared.global [%0], [%1], 16;"
        :: "r"(dst), "l"(src) : "memory");
}
#define CP_COMMIT() asm volatile("cp.async.commit_group;" ::: "memory")
#define CP_WAIT(N)  asm volatile("cp.async.wait_group %0;" :: "n"(N) : "memory")

// pack two fp32 into bf16x2 (hi) and residual bf16x2 (lo)
__device__ __forceinline__ void split_pack(float p0, float p1,
                                           uint32_t& hi2, uint32_t& lo2) {
    __nv_bfloat162 h = __floats2bfloat162_rn(p0, p1);
    float r0 = p0 - __bfloat162float(h.x);
    float r1 = p1 - __bfloat162float(h.y);
    __nv_bfloat162 l = __floats2bfloat162_rn(r0, r1);
    hi2 = *(uint32_t*)&h;
    lo2 = *(uint32_t*)&l;
}

// 64B-row swizzle: slot (16B unit) XORed with row bits -> conflict-free ldmatrix
__device__ __forceinline__ uint32_t swz64(int r, int slot) {
    return (uint32_t)(r * 64 + ((slot ^ ((r >> 1) & 3)) << 4));
}
// 128B-row swizzle (SW128)
#define SWZ128(off) ((off) ^ (((off) >> 3) & 0x70))

// ---------------------------------------------------------------------------
// Fused fp32 -> bf16 hi/lo split for x, w_qkv, w_out in ONE launch.
// ---------------------------------------------------------------------------
#define N4_X   (NT*E_/4)
#define N4_WQ  (F3*E_/4)
#define N4_WO  (E_*E_/4)

__global__ void __launch_bounds__(256) split_all_kernel(
    const float* __restrict__ x, const float* __restrict__ wq,
    const float* __restrict__ wo,
    __nv_bfloat16* __restrict__ xhi, __nv_bfloat16* __restrict__ xlo,
    __nv_bfloat16* __restrict__ wqhi, __nv_bfloat16* __restrict__ wqlo,
    __nv_bfloat16* __restrict__ wohi, __nv_bfloat16* __restrict__ wolo)
{
    int i = blockIdx.x * blockDim.x + threadIdx.x;
    const float* in; __nv_bfloat16 *hi, *lo; int off;
    if (i < N4_X)               { in = x;  hi = xhi;  lo = xlo;  off = i; }
    else if (i < N4_X + N4_WQ)  { in = wq; hi = wqhi; lo = wqlo; off = i - N4_X; }
    else if (i < N4_X + N4_WQ + N4_WO)
                                { in = wo; hi = wohi; lo = wolo; off = i - N4_X - N4_WQ; }
    else return;

    float4 v = ((const float4*)in)[off];
    float f[4] = {v.x, v.y, v.z, v.w};
    unsigned short hs[4], ls[4];
    #pragma unroll
    for (int j = 0; j < 4; j++) {
        __nv_bfloat16 h = __float2bfloat16(f[j]);
        __nv_bfloat16 l = __float2bfloat16(f[j] - __bfloat162float(h));
        hs[j] = *(unsigned short*)&h;
        ls[j] = *(unsigned short*)&l;
    }
    ((ushort4*)hi)[off] = make_ushort4(hs[0], hs[1], hs[2], hs[3]);
    ((ushort4*)lo)[off] = make_ushort4(ls[0], ls[1], ls[2], ls[3]);
}

// ---------------------------------------------------------------------------
// bf16-split mma.sync GEMM: C[M,N] = A[M,K] * B[N,K]^T.
// R13: CTA tile 64(M)x128(N), 4 warps (2m x 2n) of 32x64 -> 64 C-floats/thread
//      -> regs ~150 -> 3 CTAs/SM (3 warps/SMSP, +50% latency cover).
// K-chunk 32, 3-stage cp.async ring, swizzled 64B rows.
// ---------------------------------------------------------------------------
#define KC    32
#define ATILE (64*64)                 // 4096 B per A plane (64 rows x 64B)
#define BTILE (128*64)                // 8192 B per B plane
#define STAGEB (2*ATILE + 2*BTILE)    // 24576 per stage
#define GEMM_SMEM (3*STAGEB)          // 73728

__global__ void __launch_bounds__(128, 3) mma_gemm_kernel(
    const __nv_bfloat16* __restrict__ Ahi, const __nv_bfloat16* __restrict__ Alo,
    const __nv_bfloat16* __restrict__ Bhi, const __nv_bfloat16* __restrict__ Blo,
    float* __restrict__ Cplain, int mode)
{
    extern __shared__ char smc[];
    const uint32_t sb = smem_to_u32(smc);
    const int tid  = threadIdx.x;
    const int wid  = tid >> 5;
    const int lane = tid & 31;
    const int warp_m = (wid & 1) * 32;
    const int warp_n = (wid >> 1) * 64;
    const int row0 = blockIdx.y * 64;
    const int col0 = blockIdx.x * 128;

    float C[2][8][4];
    #pragma unroll
    for (int mi = 0; mi < 2; mi++)
        #pragma unroll
        for (int nf = 0; nf < 8; nf++)
            #pragma unroll
            for (int e = 0; e < 4; e++) C[mi][nf][e] = 0.f;

    // loader coords: A 256 slots (2/thread), B 512 slots (4/thread)
    const int slot_ld = tid & 3;

    const int NCH = E_ / KC;   // 32

    auto issue = [&](int c, int st) {
        const int k0 = c * KC;
        const uint32_t base = sb + st * STAGEB;
        #pragma unroll
        for (int l = 0; l < 2; l++) {
            int r = ((l * 128 + tid) >> 2);          // 0..63
            uint32_t so = swz64(r, slot_ld);
            size_t ga = (size_t)(row0 + r) * E_ + k0 + slot_ld * 8;
            cp16(base + 0*ATILE + so, Ahi + ga);
            cp16(base + 1*ATILE + so, Alo + ga);
        }
        #pragma unroll
        for (int l = 0; l < 4; l++) {
            int r = ((l * 128 + tid) >> 2);          // 0..127
            uint32_t so = swz64(r, slot_ld);
            size_t gb = (size_t)(col0 + r) * E_ + k0 + slot_ld * 8;
            cp16(base + 2*ATILE + so, Bhi + gb);
            cp16(base + 2*ATILE + BTILE + so, Blo + gb);
        }
    };

    issue(0, 0); CP_COMMIT();
    issue(1, 1); CP_COMMIT();

    #pragma unroll 1
    for (int c = 0; c < NCH; c++) {
        CP_WAIT(1);
        __syncthreads();

        if (c + 2 < NCH) issue(c + 2, (c + 2) % 3);
        CP_COMMIT();

        const uint32_t stbase = sb + (c % 3) * STAGEB;
        const uint32_t bAhi = stbase + 0 * ATILE;
        const uint32_t bAlo = stbase + 1 * ATILE;
        const uint32_t bBhi = stbase + 2 * ATILE;
        const uint32_t bBlo = stbase + 2 * ATILE + BTILE;

        #pragma unroll
        for (int ki = 0; ki < 2; ki++) {
            const int aslot = ki * 2 + (lane >> 4);
            uint32_t ah[2][4], al[2][4];
            #pragma unroll
            for (int mi = 0; mi < 2; mi++) {
                uint32_t ao = swz64(warp_m + mi * 16 + (lane & 15), aslot);
                ldsm_x4(ah[mi][0], ah[mi][1], ah[mi][2], ah[mi][3], bAhi + ao);
                ldsm_x4(al[mi][0], al[mi][1], al[mi][2], al[mi][3], bAlo + ao);
            }
            const int brow_off = (lane & 7) + ((lane >> 4) & 1) * 8;
            const int bslot    = ki * 2 + ((lane >> 3) & 1);
            #pragma unroll
            for (int nj = 0; nj < 4; nj++) {
                uint32_t bo = swz64(warp_n + nj * 16 + brow_off, bslot);
                uint32_t bh0, bh1, bh2, bh3, bl0, bl1, bl2, bl3;
                ldsm_x4(bh0, bh1, bh2, bh3, bBhi + bo);
                ldsm_x4(bl0, bl1, bl2, bl3, bBlo + bo);
                #pragma unroll
                for (int mi = 0; mi < 2; mi++) {
                    mma_bf16(C[mi][nj * 2],     ah[mi][0], ah[mi][1], ah[mi][2], ah[mi][3], bh0, bh1);
                    mma_bf16(C[mi][nj * 2 + 1], ah[mi][0], ah[mi][1], ah[mi][2], ah[mi][3], bh2, bh3);
                }
                #pragma unroll
                for (int mi = 0; mi < 2; mi++) {
                    mma_bf16(C[mi][nj * 2],     al[mi][0], al[mi][1], al[mi][2], al[mi][3], bh0, bh1);
                    mma_bf16(C[mi][nj * 2 + 1], al[mi][0], al[mi][1], al[mi][2], al[mi][3], bh2, bh3);
                }
                #pragma unroll
                for (int mi = 0; mi < 2; mi++) {
                    mma_bf16(C[mi][nj * 2],     ah[mi][0], ah[mi][1], ah[mi][2], ah[mi][3], bl0, bl1);
                    mma_bf16(C[mi][nj * 2 + 1], ah[mi][0], ah[mi][1], ah[mi][2], ah[mi][3], bl2, bl3);
                }
            }
        }
    }

    if (mode == 0) {
        #pragma unroll
        for (int mi = 0; mi < 2; mi++) {
            #pragma unroll
            for (int half = 0; half < 2; half++) {
                int t = row0 + warp_m + mi * 16 + (lane >> 2) + half * 8;
                int bb = t >> 11;
                int ss = t & (S_ - 1);
                #pragma unroll
                for (int nf = 0; nf < 8; nf++) {
                    int f = col0 + warp_n + nf * 8 + (lane & 3) * 2;
                    int which = f >> 10;
                    int rem = f & 1023;
                    int h = rem >> 6;
                    int d = rem & 63;
                    float v0 = C[mi][nf][half * 2];
                    float v1 = C[mi][nf][half * 2 + 1];
                    if (which == 0) { v0 *= 0.125f; v1 *= 0.125f; }
                    uint32_t hi2, lo2;
                    split_pack(v0, v1, hi2, lo2);
                    __nv_bfloat16* dhi = (which == 0) ? g_qhi : ((which == 1) ? g_khi : g_vhi);
                    __nv_bfloat16* dlo = (which == 0) ? g_qlo : ((which == 1) ? g_klo : g_vlo);
                    size_t idx = (((size_t)(bb * H_ + h)) * S_ + ss) * D_ + d;
                    *(uint32_t*)(dhi + idx) = hi2;
                    *(uint32_t*)(dlo + idx) = lo2;
                }
            }
        }
    } else {
        #pragma unroll
        for (int mi = 0; mi < 2; mi++) {
            #pragma unroll
            for (int half = 0; half < 2; half++) {
                int r = row0 + warp_m + mi * 16 + (lane >> 2) + half * 8;
                #pragma unroll
                for (int nf = 0; nf < 8; nf++) {
                    int f = col0 + warp_n + nf * 8 + (lane & 3) * 2;
                    float2 v = make_float2(C[mi][nf][half * 2],
                                           C[mi][nf][half * 2 + 1]);
                    *(float2*)(Cplain + (size_t)r * E_ + f) = v;
                }
            }
        }
    }
}

// ---------------------------------------------------------------------------
// Flash attention (causal), bf16 hi/lo split tensor cores (unchanged, best).
// CTA: 64 q-rows, 4 warps (128 thr), kv blocks of 64, 3-stage cp.async ring.
// ---------------------------------------------------------------------------
#define APL   8192                    // 64 rows x 128B, one plane
#define KVST  (4*APL)                 // Khi,Klo,Vhi,Vlo per stage = 32768
#define ATTN_SMEM (2*APL + 3*KVST)    // Q planes + 3 stages = 114688 (112KB)

__global__ void __launch_bounds__(128, 2) attn_mma_kernel()
{
    extern __shared__ char sma[];
    const uint32_t sb = smem_to_u32(sma);
    const uint32_t oQhi = 0, oQlo = APL, oKV = 2 * APL;

    const int qb = (int)gridDim.x - 1 - (int)blockIdx.x;  // longest-first
    const int bh = blockIdx.y;
    const int bb = bh >> 4;
    const int hh = bh & 15;
    const int tid  = threadIdx.x;
    const int wid  = tid >> 5;
    const int lane = tid & 31;
    const int warp_m = wid * 16;

    const __nv_bfloat16* Khb = g_khi + (size_t)bh * S_ * D_;
    const __nv_bfloat16* Klb = g_klo + (size_t)bh * S_ * D_;
    const __nv_bfloat16* Vhb = g_vhi + (size_t)bh * S_ * D_;
    const __nv_bfloat16* Vlb = g_vlo + (size_t)bh * S_ * D_;

    auto issue_kv = [&](int kb, int st) {
        const size_t base = (size_t)(kb * 64) * D_;
        const uint32_t sbase = sb + oKV + st * KVST;
        #pragma unroll
        for (int l = 0; l < 4; l++) {
            int idx = l * 128 + tid;
            int r = idx >> 3, slot = idx & 7;
            uint32_t so = (uint32_t)SWZ128(r * 128 + slot * 16);
            size_t go = base + r * D_ + slot * 8;
            cp16(sbase + 0*APL + so, Khb + go);
            cp16(sbase + 1*APL + so, Klb + go);
            cp16(sbase + 2*APL + so, Vhb + go);
            cp16(sbase + 3*APL + so, Vlb + go);
        }
    };

    issue_kv(0, 0); CP_COMMIT();
    if (qb >= 1) issue_kv(1, 1);
    CP_COMMIT();

    // ---- load Q tile (hi/lo), swizzled ----
    {
        const __nv_bfloat16* Qh = g_qhi + ((size_t)bh * S_ + qb * 64) * D_;
        const __nv_bfloat16* Ql = g_qlo + ((size_t)bh * S_ + qb * 64) * D_;
        #pragma unroll
        for (int l = 0; l < 4; l++) {
            int idx = l * 128 + tid;
            int r = idx >> 3, slot = idx & 7;
            uint32_t so = (uint32_t)SWZ128(r * 128 + slot * 16);
            *(float4*)(sma + oQhi + so) = *(const float4*)(Qh + r * D_ + slot * 8);
            *(float4*)(sma + oQlo + so) = *(const float4*)(Ql + r * D_ + slot * 8);
        }
    }
    __syncthreads();

    // ---- preload Q fragments ----
    uint32_t aqh[4][4], aql[4][4];
    #pragma unroll
    for (int ki = 0; ki < 4; ki++) {
        int row = warp_m + (lane & 15);
        int colb = (ki * 16 + (lane >> 4) * 8) * 2;
        uint32_t ao = (uint32_t)SWZ128(row * 128 + colb);
        ldsm_x4(aqh[ki][0], aqh[ki][1], aqh[ki][2], aqh[ki][3], sb + oQhi + ao);
        ldsm_x4(aql[ki][0], aql[ki][1], aql[ki][2], aql[ki][3], sb + oQlo + ao);
    }

    float m[2]  = {-1e30f, -1e30f};
    float lsum[2] = {0.f, 0.f};
    float o[8][4];
    #pragma unroll
    for (int nf = 0; nf < 8; nf++)
        #pragma unroll
        for (int e = 0; e < 4; e++) o[nf][e] = 0.f;

    #pragma unroll 1
    for (int kb = 0; kb <= qb; kb++) {
        CP_WAIT(1);
        __syncthreads();

        if (kb + 2 <= qb) issue_kv(kb + 2, (kb + 2) % 3);
        CP_COMMIT();

        const uint32_t stb = sb + oKV + (kb % 3) * KVST;
        const uint32_t bKhi = stb, bKlo = stb + APL;
        const uint32_t bVhi = stb + 2*APL, bVlo = stb + 3*APL;

        float s[8][4];
        #pragma unroll
        for (int nf = 0; nf < 8; nf++)
            #pragma unroll
            for (int e = 0; e < 4; e++) s[nf][e] = 0.f;

        #pragma unroll
        for (int ki = 0; ki < 4; ki++) {
            const int ro = (lane & 7) + ((lane >> 4) & 1) * 8;
            const int cb = (ki * 16 + ((lane >> 3) & 1) * 8) * 2;
            uint32_t kh[4][4], kl[4][4];
            #pragma unroll
            for (int nj = 0; nj < 4; nj++) {
                uint32_t ad = (uint32_t)SWZ128((nj * 16 + ro) * 128 + cb);
                ldsm_x4(kh[nj][0], kh[nj][1], kh[nj][2], kh[nj][3], bKhi + ad);
                ldsm_x4(kl[nj][0], kl[nj][1], kl[nj][2], kl[nj][3], bKlo + ad);
            }
            #pragma unroll
            for (int nj = 0; nj < 4; nj++) {
                mma_bf16(s[nj * 2],     aqh[ki][0], aqh[ki][1], aqh[ki][2], aqh[ki][3], kh[nj][0], kh[nj][1]);
                mma_bf16(s[nj * 2 + 1], aqh[ki][0], aqh[ki][1], aqh[ki][2], aqh[ki][3], kh[nj][2], kh[nj][3]);
            }
            #pragma unroll
            for (int nj = 0; nj < 4; nj++) {
                mma_bf16(s[nj * 2],     aql[ki][0], aql[ki][1], aql[ki][2], aql[ki][3], kh[nj][0], kh[nj][1]);
                mma_bf16(s[nj * 2 + 1], aql[ki][0], aql[ki][1], aql[ki][2], aql[ki][3], kh[nj][2], kh[nj][3]);
            }
            #pragma unroll
            for (int nj = 0; nj < 4; nj++) {
                mma_bf16(s[nj * 2],     aqh[ki][0], aqh[ki][1], aqh[ki][2], aqh[ki][3], kl[nj][0], kl[nj][1]);
                mma_bf16(s[nj * 2 + 1], aqh[ki][0], aqh[ki][1], aqh[ki][2], aqh[ki][3], kl[nj][2], kl[nj][3]);
            }
        }

        if (kb == qb) {
            const int qrow0 = qb * 64 + warp_m + (lane >> 2);
            #pragma unroll
            for (int nf = 0; nf < 8; nf++) {
                int kcol = kb * 64 + nf * 8 + (lane & 3) * 2;
                #pragma unroll
                for (int e = 0; e < 4; e++) {
                    int q = qrow0 + (e >> 1) * 8;
                    int kv = kcol + (e & 1);
                    if (kv > q) s[nf][e] = -1e30f;
                }
            }
        }

        #pragma unroll
        for (int h = 0; h < 2; h++) {
            float rmax = -1e30f;
            #pragma unroll
            for (int nf = 0; nf < 8; nf++) {
                rmax = fmaxf(rmax, s[nf][2*h]);
                rmax = fmaxf(rmax, s[nf][2*h+1]);
            }
            rmax = fmaxf(rmax, __shfl_xor_sync(0xffffffffu, rmax, 1));
            rmax = fmaxf(rmax, __shfl_xor_sync(0xffffffffu, rmax, 2));

            float mnew = fmaxf(m[h], rmax);
            float corr = __expf(m[h] - mnew);
            m[h] = mnew;

            float rsum = 0.f;
            #pragma unroll
            for (int nf = 0; nf < 8; nf++) {
                float p0 = __expf(s[nf][2*h]   - mnew);
                float p1 = __expf(s[nf][2*h+1] - mnew);
                s[nf][2*h]   = p0;
                s[nf][2*h+1] = p1;
                rsum += p0 + p1;
            }
            rsum += __shfl_xor_sync(0xffffffffu, rsum, 1);
            rsum += __shfl_xor_sync(0xffffffffu, rsum, 2);
            lsum[h] = lsum[h] * corr + rsum;

            #pragma unroll
            for (int nf = 0; nf < 8; nf++) {
                o[nf][2*h]   *= corr;
                o[nf][2*h+1] *= corr;
            }
        }

        #pragma unroll
        for (int ki = 0; ki < 4; ki++) {
            uint32_t aph[4], apl[4];
            split_pack(s[2*ki][0],   s[2*ki][1],   aph[0], apl[0]);
            split_pack(s[2*ki][2],   s[2*ki][3],   aph[1], apl[1]);
            split_pack(s[2*ki+1][0], s[2*ki+1][1], aph[2], apl[2]);
            split_pack(s[2*ki+1][2], s[2*ki+1][3], aph[3], apl[3]);

            const int rowv = ki * 16 + (lane & 7) + ((lane >> 3) & 1) * 8;
            const int cb0  = ((lane >> 4) & 1) * 16;
            uint32_t vh[4][4], vl[4][4];
            #pragma unroll
            for (int nj = 0; nj < 4; nj++) {
                uint32_t ad = (uint32_t)SWZ128(rowv * 128 + cb0 + nj * 32);
                ldsm_x4_trans(vh[nj][0], vh[nj][1], vh[nj][2], vh[nj][3], bVhi + ad);
                ldsm_x4_trans(vl[nj][0], vl[nj][1], vl[nj][2], vl[nj][3], bVlo + ad);
            }
            #pragma unroll
            for (int nj = 0; nj < 4; nj++) {
                mma_bf16(o[nj * 2],     aph[0], aph[1], aph[2], aph[3], vh[nj][0], vh[nj][1]);
                mma_bf16(o[nj * 2 + 1], aph[0], aph[1], aph[2], aph[3], vh[nj][2], vh[nj][3]);
            }
            #pragma unroll
            for (int nj = 0; nj < 4; nj++) {
                mma_bf16(o[nj * 2],     apl[0], apl[1], apl[2], apl[3], vh[nj][0], vh[nj][1]);
                mma_bf16(o[nj * 2 + 1], apl[0], apl[1], apl[2], apl[3], vh[nj][2], vh[nj][3]);
            }
            #pragma unroll
            for (int nj = 0; nj < 4; nj++) {
                mma_bf16(o[nj * 2],     aph[0], aph[1], aph[2], aph[3], vl[nj][0], vl[nj][1]);
                mma_bf16(o[nj * 2 + 1], aph[0], aph[1], aph[2], aph[3], vl[nj][2], vl[nj][3]);
            }
        }
    }

    // ---- epilogue: O / l, split to bf16 hi/lo planes [B,S,E] ----
    #pragma unroll
    for (int h = 0; h < 2; h++) {
        float inv = 1.0f / lsum[h];
        int r = warp_m + (lane >> 2) + h * 8;
        size_t t = (size_t)(bb * S_ + qb * 64 + r);
        #pragma unroll
        for (int nf = 0; nf < 8; nf++) {
            int dcol = hh * 64 + nf * 8 + (lane & 3) * 2;
            uint32_t hi2, lo2;
            split_pack(o[nf][2*h] * inv, o[nf][2*h+1] * inv, hi2, lo2);
            *(uint32_t*)(g_ohi + t * E_ + dcol) = hi2;
            *(uint32_t*)(g_olo + t * E_ + dcol) = lo2;
        }
    }
}

// ---------------------------------------------------------------------------
extern "C" void kernel_launch(void* const* d_in, const int* in_sizes, int n_in,
                              void* d_out, int out_size)
{
    const float* x     = (const float*)d_in[0];   // [B,S,E]
    const float* w_qkv = (const float*)d_in[1];   // [3E,E]
    const float* w_out = (const float*)d_in[2];   // [E,E]
    float* out = (float*)d_out;                   // [B,S,E]

    __nv_bfloat16 *xhi, *xlo, *wqhi, *wqlo, *wohi, *wolo, *ohi, *olo;
    cudaGetSymbolAddress((void**)&xhi,  g_xhi);
    cudaGetSymbolAddress((void**)&xlo,  g_xlo);
    cudaGetSymbolAddress((void**)&wqhi, g_wqhi);
    cudaGetSymbolAddress((void**)&wqlo, g_wqlo);
    cudaGetSymbolAddress((void**)&wohi, g_wohi);
    cudaGetSymbolAddress((void**)&wolo, g_wolo);
    cudaGetSymbolAddress((void**)&ohi,  g_ohi);
    cudaGetSymbolAddress((void**)&olo,  g_olo);

    static bool attr_set = false;
    if (!attr_set) {
        cudaFuncSetAttribute(mma_gemm_kernel,
                             cudaFuncAttributeMaxDynamicSharedMemorySize,
                             GEMM_SMEM);
        cudaFuncSetAttribute(attn_mma_kernel,
                             cudaFuncAttributeMaxDynamicSharedMemorySize,
                             ATTN_SMEM);
        attr_set = true;
    }

    // 0) fused fp32 -> bf16 hi/lo splits (one launch)
    {
        int total4 = N4_X + N4_WQ + N4_WO;
        split_all_kernel<<<(total4 + 255) / 256, 256>>>(
            x, w_qkv, w_out, xhi, xlo, wqhi, wqlo, wohi, wolo);
    }

    // 1) QKV projection (tensor cores) -> bf16 hi/lo q/k/v planes
    {
        dim3 grid(F3 / 128, NT / 64);    // (24, 64)
        mma_gemm_kernel<<<grid, 128, GEMM_SMEM>>>(
            xhi, xlo, wqhi, wqlo, nullptr, 0);
    }

    // 2) Flash attention (causal, tensor cores) -> bf16 hi/lo O planes
    {
        dim3 grid(S_ / 64, B_ * H_);     // (32, 32)
        attn_mma_kernel<<<grid, 128, ATTN_SMEM>>>();
    }

    // 3) Output projection (tensor cores) -> fp32 out
    {
        dim3 grid(E_ / 128, NT / 64);    // (8, 64)
        mma_gemm_kernel<<<grid, 128, GEMM_SMEM>>>(
            ohi, olo, wohi, wolo, out, 1);
    }
}

// round 14
// speedup vs baseline: 1.1978x; 1.1978x over previous
#include <cuda_runtime.h>
#include <cuda_bf16.h>
#include <cstdint>
#include <math.h>

// Problem constants
#define B_  2
#define S_  2048
#define E_  1024
#define H_  16
#define D_  64
#define NT  (B_*S_)      // 4096 tokens
#define F3  (3*E_)       // 3072 qkv features

// ---------------------------------------------------------------------------
// Device-global scratch (no allocation allowed)
// ---------------------------------------------------------------------------
#define QKV_ELEMS ((size_t)B_*H_*S_*D_)
__device__ __nv_bfloat16 g_qhi[QKV_ELEMS], g_qlo[QKV_ELEMS];
__device__ __nv_bfloat16 g_khi[QKV_ELEMS], g_klo[QKV_ELEMS];
__device__ __nv_bfloat16 g_vhi[QKV_ELEMS], g_vlo[QKV_ELEMS];

__device__ float g_x32[(size_t)NT*E_];     // tf32-rounded activations
__device__ float g_wq32[(size_t)F3*E_];    // tf32-rounded qkv weight
__device__ float g_wo32[(size_t)E_*E_];    // tf32-rounded out weight
__device__ float g_o32[(size_t)NT*E_];     // tf32-rounded attention output

// ---------------------------------------------------------------------------
// Warp-level tensor-core helpers (portable PTX: sm_80+, assembles on sm_103)
// ---------------------------------------------------------------------------
__device__ __forceinline__ uint32_t smem_to_u32(const void* p) {
    uint32_t a;
    asm("{ .reg .u64 t; cvta.to.shared.u64 t, %1; cvt.u32.u64 %0, t; }"
        : "=r"(a) : "l"(p));
    return a;
}

__device__ __forceinline__ void ldsm_x4(uint32_t& r0, uint32_t& r1,
                                        uint32_t& r2, uint32_t& r3,
                                        uint32_t addr) {
    asm volatile("ldmatrix.sync.aligned.m8n8.x4.shared.b16 {%0,%1,%2,%3}, [%4];"
        : "=r"(r0), "=r"(r1), "=r"(r2), "=r"(r3) : "r"(addr));
}
__device__ __forceinline__ void ldsm_x4_trans(uint32_t& r0, uint32_t& r1,
                                              uint32_t& r2, uint32_t& r3,
                                              uint32_t addr) {
    asm volatile("ldmatrix.sync.aligned.m8n8.x4.trans.shared.b16 {%0,%1,%2,%3}, [%4];"
        : "=r"(r0), "=r"(r1), "=r"(r2), "=r"(r3) : "r"(addr));
}

__device__ __forceinline__ void mma_bf16(float c[4],
                                         uint32_t a0, uint32_t a1,
                                         uint32_t a2, uint32_t a3,
                                         uint32_t b0, uint32_t b1) {
    asm volatile(
        "mma.sync.aligned.m16n8k16.row.col.f32.bf16.bf16.f32 "
        "{%0,%1,%2,%3}, {%4,%5,%6,%7}, {%8,%9}, {%0,%1,%2,%3};"
        : "+f"(c[0]), "+f"(c[1]), "+f"(c[2]), "+f"(c[3])
        : "r"(a0), "r"(a1), "r"(a2), "r"(a3), "r"(b0), "r"(b1));
}

__device__ __forceinline__ void mma_tf32(float c[4],
                                         uint32_t a0, uint32_t a1,
                                         uint32_t a2, uint32_t a3,
                                         uint32_t b0, uint32_t b1) {
    asm volatile(
        "mma.sync.aligned.m16n8k8.row.col.f32.tf32.tf32.f32 "
        "{%0,%1,%2,%3}, {%4,%5,%6,%7}, {%8,%9}, {%0,%1,%2,%3};"
        : "+f"(c[0]), "+f"(c[1]), "+f"(c[2]), "+f"(c[3])
        : "r"(a0), "r"(a1), "r"(a2), "r"(a3), "r"(b0), "r"(b1));
}

__device__ __forceinline__ float rna_tf32(float f) {
    uint32_t u;
    asm("cvt.rna.tf32.f32 %0, %1;" : "=r"(u) : "f"(f));
    return __uint_as_float(u);
}

__device__ __forceinline__ void cp16(uint32_t dst, const void* src) {
    asm volatile("cp.async.cg.shared.global [%0], [%1], 16;"
        :: "r"(dst), "l"(src) : "memory");
}
#define CP_COMMIT() asm volatile("cp.async.commit_group;" ::: "memory")
#define CP_WAIT(N)  asm volatile("cp.async.wait_group %0;" :: "n"(N) : "memory")

// pack two fp32 into bf16x2 (hi) and residual bf16x2 (lo)
__device__ __forceinline__ void split_pack(float p0, float p1,
                                           uint32_t& hi2, uint32_t& lo2) {
    __nv_bfloat162 h = __floats2bfloat162_rn(p0, p1);
    float r0 = p0 - __bfloat162float(h.x);
    float r1 = p1 - __bfloat162float(h.y);
    __nv_bfloat162 l = __floats2bfloat162_rn(r0, r1);
    hi2 = *(uint32_t*)&h;
    lo2 = *(uint32_t*)&l;
}

// 128B-row swizzle (SW128)
#define SWZ128(off) ((off) ^ (((off) >> 3) & 0x70))

// ---------------------------------------------------------------------------
// Fused fp32 -> tf32-rounded fp32 for x, w_qkv, w_out in ONE launch.
// ---------------------------------------------------------------------------
#define N4_X   (NT*E_/4)
#define N4_WQ  (F3*E_/4)
#define N4_WO  (E_*E_/4)

__global__ void __launch_bounds__(256) round_all_kernel(
    const float* __restrict__ x, const float* __restrict__ wq,
    const float* __restrict__ wo,
    float* __restrict__ x32, float* __restrict__ wq32,
    float* __restrict__ wo32)
{
    int i = blockIdx.x * blockDim.x + threadIdx.x;
    const float* in; float* out; int off;
    if (i < N4_X)               { in = x;  out = x32;  off = i; }
    else if (i < N4_X + N4_WQ)  { in = wq; out = wq32; off = i - N4_X; }
    else if (i < N4_X + N4_WQ + N4_WO)
                                { in = wo; out = wo32; off = i - N4_X - N4_WQ; }
    else return;

    float4 v = ((const float4*)in)[off];
    v.x = rna_tf32(v.x); v.y = rna_tf32(v.y);
    v.z = rna_tf32(v.z); v.w = rna_tf32(v.w);
    ((float4*)out)[off] = v;
}

// ---------------------------------------------------------------------------
// tf32 single-pass mma.sync GEMM: C[M,N] = A[M,K] * B[N,K]^T.
// CTA tile 128x128, K-chunk 32 fp32 (=128B rows, SW128), 4 warps (2m x 2n)
// of 64x64, 3-stage cp.async ring. 1 pass instead of 3 -> 1.5x fewer
// tensor cycles than the bf16-split scheme.
// mode 0: QKV -> split into g_{q,k,v}{hi,lo} bf16 planes (Q scaled 0.125)
// mode 1: plain fp32 store to Cplain.
// ---------------------------------------------------------------------------
#define KC    32
#define TIL32 (128*128)               // 16384 bytes per fp32 tile
#define STG32 (2*TIL32)               // 32768 per stage (A,B)
#define GEMM_SMEM (3*STG32)           // 98304

__global__ void __launch_bounds__(128, 2) mma_gemm_kernel(
    const float* __restrict__ A32, const float* __restrict__ B32,
    float* __restrict__ Cplain, int mode)
{
    extern __shared__ char smc[];
    const uint32_t sb = smem_to_u32(smc);
    const int tid  = threadIdx.x;
    const int wid  = tid >> 5;
    const int lane = tid & 31;
    const int warp_m = (wid & 1) * 64;
    const int warp_n = (wid >> 1) * 64;
    const int row0 = blockIdx.y * 128;
    const int col0 = blockIdx.x * 128;

    float C[4][8][4];
    #pragma unroll
    for (int mi = 0; mi < 4; mi++)
        #pragma unroll
        for (int nf = 0; nf < 8; nf++)
            #pragma unroll
            for (int e = 0; e < 4; e++) C[mi][nf][e] = 0.f;

    const int NCH = E_ / KC;   // 32

    // loader: A 1024 slots + B 1024 slots, 16 cp16/thread
    auto issue = [&](int c, int st) {
        const int k0 = c * KC;
        const uint32_t base = sb + st * STG32;
        #pragma unroll
        for (int l = 0; l < 8; l++) {
            int idx = l * 128 + tid;
            int r = idx >> 3, slot = idx & 7;
            uint32_t so = (uint32_t)SWZ128(r * 128 + slot * 16);
            cp16(base + so,         A32 + (size_t)(row0 + r) * E_ + k0 + slot * 4);
            cp16(base + TIL32 + so, B32 + (size_t)(col0 + r) * E_ + k0 + slot * 4);
        }
    };

    issue(0, 0); CP_COMMIT();
    issue(1, 1); CP_COMMIT();

    #pragma unroll 1
    for (int c = 0; c < NCH; c++) {
        CP_WAIT(1);
        __syncthreads();

        if (c + 2 < NCH) issue(c + 2, (c + 2) % 3);
        CP_COMMIT();

        const uint32_t bA = sb + (c % 3) * STG32;
        const uint32_t bB = bA + TIL32;

        #pragma unroll
        for (int ki = 0; ki < 4; ki++) {
            // A fragments: 4 m16 tiles, tf32 a0..a3 via b16 ldmatrix
            const int acolb = ki * 32 + (lane >> 4) * 16;
            uint32_t a[4][4];
            #pragma unroll
            for (int mi = 0; mi < 4; mi++) {
                uint32_t ao = (uint32_t)SWZ128(
                    (warp_m + mi * 16 + (lane & 15)) * 128 + acolb);
                ldsm_x4(a[mi][0], a[mi][1], a[mi][2], a[mi][3], bA + ao);
            }
            // B fragments: x4 covers two n8 tiles per load
            const int brow_off = ((lane >> 4) & 1) * 8 + (lane & 7);
            const int bcolb    = ki * 32 + ((lane >> 3) & 1) * 16;
            #pragma unroll
            for (int njp = 0; njp < 4; njp++) {
                uint32_t bo = (uint32_t)SWZ128(
                    (warp_n + njp * 16 + brow_off) * 128 + bcolb);
                uint32_t b0, b1, b2, b3;
                ldsm_x4(b0, b1, b2, b3, bB + bo);
                #pragma unroll
                for (int mi = 0; mi < 4; mi++) {
                    mma_tf32(C[mi][njp * 2],     a[mi][0], a[mi][1], a[mi][2], a[mi][3], b0, b1);
                    mma_tf32(C[mi][njp * 2 + 1], a[mi][0], a[mi][1], a[mi][2], a[mi][3], b2, b3);
                }
            }
        }
    }

    if (mode == 0) {
        #pragma unroll
        for (int mi = 0; mi < 4; mi++) {
            #pragma unroll
            for (int half = 0; half < 2; half++) {
                int t = row0 + warp_m + mi * 16 + (lane >> 2) + half * 8;
                int bb = t >> 11;
                int ss = t & (S_ - 1);
                #pragma unroll
                for (int nf = 0; nf < 8; nf++) {
                    int f = col0 + warp_n + nf * 8 + (lane & 3) * 2;
                    int which = f >> 10;
                    int rem = f & 1023;
                    int h = rem >> 6;
                    int d = rem & 63;
                    float v0 = C[mi][nf][half * 2];
                    float v1 = C[mi][nf][half * 2 + 1];
                    if (which == 0) { v0 *= 0.125f; v1 *= 0.125f; }
                    uint32_t hi2, lo2;
                    split_pack(v0, v1, hi2, lo2);
                    __nv_bfloat16* dhi = (which == 0) ? g_qhi : ((which == 1) ? g_khi : g_vhi);
                    __nv_bfloat16* dlo = (which == 0) ? g_qlo : ((which == 1) ? g_klo : g_vlo);
                    size_t idx = (((size_t)(bb * H_ + h)) * S_ + ss) * D_ + d;
                    *(uint32_t*)(dhi + idx) = hi2;
                    *(uint32_t*)(dlo + idx) = lo2;
                }
            }
        }
    } else {
        #pragma unroll
        for (int mi = 0; mi < 4; mi++) {
            #pragma unroll
            for (int half = 0; half < 2; half++) {
                int r = row0 + warp_m + mi * 16 + (lane >> 2) + half * 8;
                #pragma unroll
                for (int nf = 0; nf < 8; nf++) {
                    int f = col0 + warp_n + nf * 8 + (lane & 3) * 2;
                    float2 v = make_float2(C[mi][nf][half * 2],
                                           C[mi][nf][half * 2 + 1]);
                    *(float2*)(Cplain + (size_t)r * E_ + f) = v;
                }
            }
        }
    }
}

// ---------------------------------------------------------------------------
// Flash attention (causal), bf16 hi/lo split tensor cores (R12 best, 3-pass).
// CTA: 64 q-rows, 4 warps (128 thr), kv blocks of 64, 3-stage cp.async ring.
// Epilogue writes tf32-rounded fp32 to g_o32 for the tf32 out-proj.
// ---------------------------------------------------------------------------
#define APL   8192                    // 64 rows x 128B, one plane
#define KVST  (4*APL)                 // Khi,Klo,Vhi,Vlo per stage = 32768
#define ATTN_SMEM (2*APL + 3*KVST)    // Q planes + 3 stages = 114688 (112KB)

__global__ void __launch_bounds__(128, 2) attn_mma_kernel()
{
    extern __shared__ char sma[];
    const uint32_t sb = smem_to_u32(sma);
    const uint32_t oQhi = 0, oQlo = APL, oKV = 2 * APL;

    const int qb = (int)gridDim.x - 1 - (int)blockIdx.x;  // longest-first
    const int bh = blockIdx.y;
    const int bb = bh >> 4;
    const int hh = bh & 15;
    const int tid  = threadIdx.x;
    const int wid  = tid >> 5;
    const int lane = tid & 31;
    const int warp_m = wid * 16;

    const __nv_bfloat16* Khb = g_khi + (size_t)bh * S_ * D_;
    const __nv_bfloat16* Klb = g_klo + (size_t)bh * S_ * D_;
    const __nv_bfloat16* Vhb = g_vhi + (size_t)bh * S_ * D_;
    const __nv_bfloat16* Vlb = g_vlo + (size_t)bh * S_ * D_;

    auto issue_kv = [&](int kb, int st) {
        const size_t base = (size_t)(kb * 64) * D_;
        const uint32_t sbase = sb + oKV + st * KVST;
        #pragma unroll
        for (int l = 0; l < 4; l++) {
            int idx = l * 128 + tid;
            int r = idx >> 3, slot = idx & 7;
            uint32_t so = (uint32_t)SWZ128(r * 128 + slot * 16);
            size_t go = base + r * D_ + slot * 8;
            cp16(sbase + 0*APL + so, Khb + go);
            cp16(sbase + 1*APL + so, Klb + go);
            cp16(sbase + 2*APL + so, Vhb + go);
            cp16(sbase + 3*APL + so, Vlb + go);
        }
    };

    issue_kv(0, 0); CP_COMMIT();
    if (qb >= 1) issue_kv(1, 1);
    CP_COMMIT();

    // ---- load Q tile (hi/lo), swizzled ----
    {
        const __nv_bfloat16* Qh = g_qhi + ((size_t)bh * S_ + qb * 64) * D_;
        const __nv_bfloat16* Ql = g_qlo + ((size_t)bh * S_ + qb * 64) * D_;
        #pragma unroll
        for (int l = 0; l < 4; l++) {
            int idx = l * 128 + tid;
            int r = idx >> 3, slot = idx & 7;
            uint32_t so = (uint32_t)SWZ128(r * 128 + slot * 16);
            *(float4*)(sma + oQhi + so) = *(const float4*)(Qh + r * D_ + slot * 8);
            *(float4*)(sma + oQlo + so) = *(const float4*)(Ql + r * D_ + slot * 8);
        }
    }
    __syncthreads();

    // ---- preload Q fragments ----
    uint32_t aqh[4][4], aql[4][4];
    #pragma unroll
    for (int ki = 0; ki < 4; ki++) {
        int row = warp_m + (lane & 15);
        int colb = (ki * 16 + (lane >> 4) * 8) * 2;
        uint32_t ao = (uint32_t)SWZ128(row * 128 + colb);
        ldsm_x4(aqh[ki][0], aqh[ki][1], aqh[ki][2], aqh[ki][3], sb + oQhi + ao);
        ldsm_x4(aql[ki][0], aql[ki][1], aql[ki][2], aql[ki][3], sb + oQlo + ao);
    }

    float m[2]  = {-1e30f, -1e30f};
    float lsum[2] = {0.f, 0.f};
    float o[8][4];
    #pragma unroll
    for (int nf = 0; nf < 8; nf++)
        #pragma unroll
        for (int e = 0; e < 4; e++) o[nf][e] = 0.f;

    #pragma unroll 1
    for (int kb = 0; kb <= qb; kb++) {
        CP_WAIT(1);
        __syncthreads();

        if (kb + 2 <= qb) issue_kv(kb + 2, (kb + 2) % 3);
        CP_COMMIT();

        const uint32_t stb = sb + oKV + (kb % 3) * KVST;
        const uint32_t bKhi = stb, bKlo = stb + APL;
        const uint32_t bVhi = stb + 2*APL, bVlo = stb + 3*APL;

        float s[8][4];
        #pragma unroll
        for (int nf = 0; nf < 8; nf++)
            #pragma unroll
            for (int e = 0; e < 4; e++) s[nf][e] = 0.f;

        #pragma unroll
        for (int ki = 0; ki < 4; ki++) {
            const int ro = (lane & 7) + ((lane >> 4) & 1) * 8;
            const int cb = (ki * 16 + ((lane >> 3) & 1) * 8) * 2;
            uint32_t kh[4][4], kl[4][4];
            #pragma unroll
            for (int nj = 0; nj < 4; nj++) {
                uint32_t ad = (uint32_t)SWZ128((nj * 16 + ro) * 128 + cb);
                ldsm_x4(kh[nj][0], kh[nj][1], kh[nj][2], kh[nj][3], bKhi + ad);
                ldsm_x4(kl[nj][0], kl[nj][1], kl[nj][2], kl[nj][3], bKlo + ad);
            }
            #pragma unroll
            for (int nj = 0; nj < 4; nj++) {
                mma_bf16(s[nj * 2],     aqh[ki][0], aqh[ki][1], aqh[ki][2], aqh[ki][3], kh[nj][0], kh[nj][1]);
                mma_bf16(s[nj * 2 + 1], aqh[ki][0], aqh[ki][1], aqh[ki][2], aqh[ki][3], kh[nj][2], kh[nj][3]);
            }
            #pragma unroll
            for (int nj = 0; nj < 4; nj++) {
                mma_bf16(s[nj * 2],     aql[ki][0], aql[ki][1], aql[ki][2], aql[ki][3], kh[nj][0], kh[nj][1]);
                mma_bf16(s[nj * 2 + 1], aql[ki][0], aql[ki][1], aql[ki][2], aql[ki][3], kh[nj][2], kh[nj][3]);
            }
            #pragma unroll
            for (int nj = 0; nj < 4; nj++) {
                mma_bf16(s[nj * 2],     aqh[ki][0], aqh[ki][1], aqh[ki][2], aqh[ki][3], kl[nj][0], kl[nj][1]);
                mma_bf16(s[nj * 2 + 1], aqh[ki][0], aqh[ki][1], aqh[ki][2], aqh[ki][3], kl[nj][2], kl[nj][3]);
            }
        }

        if (kb == qb) {
            const int qrow0 = qb * 64 + warp_m + (lane >> 2);
            #pragma unroll
            for (int nf = 0; nf < 8; nf++) {
                int kcol = kb * 64 + nf * 8 + (lane & 3) * 2;
                #pragma unroll
                for (int e = 0; e < 4; e++) {
                    int q = qrow0 + (e >> 1) * 8;
                    int kv = kcol + (e & 1);
                    if (kv > q) s[nf][e] = -1e30f;
                }
            }
        }

        #pragma unroll
        for (int h = 0; h < 2; h++) {
            float rmax = -1e30f;
            #pragma unroll
            for (int nf = 0; nf < 8; nf++) {
                rmax = fmaxf(rmax, s[nf][2*h]);
                rmax = fmaxf(rmax, s[nf][2*h+1]);
            }
            rmax = fmaxf(rmax, __shfl_xor_sync(0xffffffffu, rmax, 1));
            rmax = fmaxf(rmax, __shfl_xor_sync(0xffffffffu, rmax, 2));

            float mnew = fmaxf(m[h], rmax);
            float corr = __expf(m[h] - mnew);
            m[h] = mnew;

            float rsum = 0.f;
            #pragma unroll
            for (int nf = 0; nf < 8; nf++) {
                float p0 = __expf(s[nf][2*h]   - mnew);
                float p1 = __expf(s[nf][2*h+1] - mnew);
                s[nf][2*h]   = p0;
                s[nf][2*h+1] = p1;
                rsum += p0 + p1;
            }
            rsum += __shfl_xor_sync(0xffffffffu, rsum, 1);
            rsum += __shfl_xor_sync(0xffffffffu, rsum, 2);
            lsum[h] = lsum[h] * corr + rsum;

            #pragma unroll
            for (int nf = 0; nf < 8; nf++) {
                o[nf][2*h]   *= corr;
                o[nf][2*h+1] *= corr;
            }
        }

        #pragma unroll
        for (int ki = 0; ki < 4; ki++) {
            uint32_t aph[4], apl[4];
            split_pack(s[2*ki][0],   s[2*ki][1],   aph[0], apl[0]);
            split_pack(s[2*ki][2],   s[2*ki][3],   aph[1], apl[1]);
            split_pack(s[2*ki+1][0], s[2*ki+1][1], aph[2], apl[2]);
            split_pack(s[2*ki+1][2], s[2*ki+1][3], aph[3], apl[3]);

            const int rowv = ki * 16 + (lane & 7) + ((lane >> 3) & 1) * 8;
            const int cb0  = ((lane >> 4) & 1) * 16;
            uint32_t vh[4][4], vl[4][4];
            #pragma unroll
            for (int nj = 0; nj < 4; nj++) {
                uint32_t ad = (uint32_t)SWZ128(rowv * 128 + cb0 + nj * 32);
                ldsm_x4_trans(vh[nj][0], vh[nj][1], vh[nj][2], vh[nj][3], bVhi + ad);
                ldsm_x4_trans(vl[nj][0], vl[nj][1], vl[nj][2], vl[nj][3], bVlo + ad);
            }
            #pragma unroll
            for (int nj = 0; nj < 4; nj++) {
                mma_bf16(o[nj * 2],     aph[0], aph[1], aph[2], aph[3], vh[nj][0], vh[nj][1]);
                mma_bf16(o[nj * 2 + 1], aph[0], aph[1], aph[2], aph[3], vh[nj][2], vh[nj][3]);
            }
            #pragma unroll
            for (int nj = 0; nj < 4; nj++) {
                mma_bf16(o[nj * 2],     apl[0], apl[1], apl[2], apl[3], vh[nj][0], vh[nj][1]);
                mma_bf16(o[nj * 2 + 1], apl[0], apl[1], apl[2], apl[3], vh[nj][2], vh[nj][3]);
            }
            #pragma unroll
            for (int nj = 0; nj < 4; nj++) {
                mma_bf16(o[nj * 2],     aph[0], aph[1], aph[2], aph[3], vl[nj][0], vl[nj][1]);
                mma_bf16(o[nj * 2 + 1], aph[0], aph[1], aph[2], aph[3], vl[nj][2], vl[nj][3]);
            }
        }
    }

    // ---- epilogue: O / l, tf32-rounded fp32 to g_o32 [B,S,E] ----
    #pragma unroll
    for (int h = 0; h < 2; h++) {
        float inv = 1.0f / lsum[h];
        int r = warp_m + (lane >> 2) + h * 8;
        size_t t = (size_t)(bb * S_ + qb * 64 + r);
        #pragma unroll
        for (int nf = 0; nf < 8; nf++) {
            int dcol = hh * 64 + nf * 8 + (lane & 3) * 2;
            float2 v = make_float2(rna_tf32(o[nf][2*h] * inv),
                                   rna_tf32(o[nf][2*h+1] * inv));
            *(float2*)(g_o32 + t * E_ + dcol) = v;
        }
    }
}

// ---------------------------------------------------------------------------
extern "C" void kernel_launch(void* const* d_in, const int* in_sizes, int n_in,
                              void* d_out, int out_size)
{
    const float* x     = (const float*)d_in[0];   // [B,S,E]
    const float* w_qkv = (const float*)d_in[1];   // [3E,E]
    const float* w_out = (const float*)d_in[2];   // [E,E]
    float* out = (float*)d_out;                   // [B,S,E]

    float *x32, *wq32, *wo32, *o32;
    cudaGetSymbolAddress((void**)&x32,  g_x32);
    cudaGetSymbolAddress((void**)&wq32, g_wq32);
    cudaGetSymbolAddress((void**)&wo32, g_wo32);
    cudaGetSymbolAddress((void**)&o32,  g_o32);

    static bool attr_set = false;
    if (!attr_set) {
        cudaFuncSetAttribute(mma_gemm_kernel,
                             cudaFuncAttributeMaxDynamicSharedMemorySize,
                             GEMM_SMEM);
        cudaFuncSetAttribute(attn_mma_kernel,
                             cudaFuncAttributeMaxDynamicSharedMemorySize,
                             ATTN_SMEM);
        attr_set = true;
    }

    // 0) fused fp32 -> tf32-rounded fp32 (one launch)
    {
        int total4 = N4_X + N4_WQ + N4_WO;
        round_all_kernel<<<(total4 + 255) / 256, 256>>>(
            x, w_qkv, w_out, x32, wq32, wo32);
    }

    // 1) QKV projection (tf32 single-pass) -> bf16 hi/lo q/k/v planes
    {
        dim3 grid(F3 / 128, NT / 128);   // (24, 32)
        mma_gemm_kernel<<<grid, 128, GEMM_SMEM>>>(x32, wq32, nullptr, 0);
    }

    // 2) Flash attention (causal, bf16 3-pass) -> tf32-rounded fp32 O
    {
        dim3 grid(S_ / 64, B_ * H_);     // (32, 32)
        attn_mma_kernel<<<grid, 128, ATTN_SMEM>>>();
    }

    // 3) Output projection (tf32 single-pass) -> fp32 out
    {
        dim3 grid(E_ / 128, NT / 128);   // (8, 32)
        mma_gemm_kernel<<<grid, 128, GEMM_SMEM>>>(o32, wo32, out, 1);
    }
}

// round 15
// speedup vs baseline: 1.2070x; 1.0076x over previous
#include <cuda_runtime.h>
#include <cuda_bf16.h>
#include <cstdint>
#include <math.h>

// Problem constants
#define B_  2
#define S_  2048
#define E_  1024
#define H_  16
#define D_  64
#define NT  (B_*S_)      // 4096 tokens
#define F3  (3*E_)       // 3072 qkv features

// ---------------------------------------------------------------------------
// Device-global scratch (no allocation allowed)
// ---------------------------------------------------------------------------
#define QKV_ELEMS ((size_t)B_*H_*S_*D_)
__device__ float g_q32[QKV_ELEMS];            // tf32-rounded, pre-scaled Q
__device__ float g_k32[QKV_ELEMS];            // tf32-rounded K
__device__ __nv_bfloat16 g_vhi[QKV_ELEMS], g_vlo[QKV_ELEMS];
__device__ float g_o[(size_t)NT*E_];          // attention output (fp32)

// ---------------------------------------------------------------------------
// Warp-level tensor-core helpers (portable PTX: sm_80+, assembles on sm_103)
// ---------------------------------------------------------------------------
__device__ __forceinline__ uint32_t smem_to_u32(const void* p) {
    uint32_t a;
    asm("{ .reg .u64 t; cvta.to.shared.u64 t, %1; cvt.u32.u64 %0, t; }"
        : "=r"(a) : "l"(p));
    return a;
}

__device__ __forceinline__ void ldsm_x4(uint32_t& r0, uint32_t& r1,
                                        uint32_t& r2, uint32_t& r3,
                                        uint32_t addr) {
    asm volatile("ldmatrix.sync.aligned.m8n8.x4.shared.b16 {%0,%1,%2,%3}, [%4];"
        : "=r"(r0), "=r"(r1), "=r"(r2), "=r"(r3) : "r"(addr));
}
__device__ __forceinline__ void ldsm_x4_trans(uint32_t& r0, uint32_t& r1,
                                              uint32_t& r2, uint32_t& r3,
                                              uint32_t addr) {
    asm volatile("ldmatrix.sync.aligned.m8n8.x4.trans.shared.b16 {%0,%1,%2,%3}, [%4];"
        : "=r"(r0), "=r"(r1), "=r"(r2), "=r"(r3) : "r"(addr));
}

__device__ __forceinline__ void mma_bf16(float c[4],
                                         uint32_t a0, uint32_t a1,
                                         uint32_t a2, uint32_t a3,
                                         uint32_t b0, uint32_t b1) {
    asm volatile(
        "mma.sync.aligned.m16n8k16.row.col.f32.bf16.bf16.f32 "
        "{%0,%1,%2,%3}, {%4,%5,%6,%7}, {%8,%9}, {%0,%1,%2,%3};"
        : "+f"(c[0]), "+f"(c[1]), "+f"(c[2]), "+f"(c[3])
        : "r"(a0), "r"(a1), "r"(a2), "r"(a3), "r"(b0), "r"(b1));
}

__device__ __forceinline__ void mma_tf32(float c[4],
                                         uint32_t a0, uint32_t a1,
                                         uint32_t a2, uint32_t a3,
                                         uint32_t b0, uint32_t b1) {
    asm volatile(
        "mma.sync.aligned.m16n8k8.row.col.f32.tf32.tf32.f32 "
        "{%0,%1,%2,%3}, {%4,%5,%6,%7}, {%8,%9}, {%0,%1,%2,%3};"
        : "+f"(c[0]), "+f"(c[1]), "+f"(c[2]), "+f"(c[3])
        : "r"(a0), "r"(a1), "r"(a2), "r"(a3), "r"(b0), "r"(b1));
}

__device__ __forceinline__ float rna_tf32(float f) {
    uint32_t u;
    asm("cvt.rna.tf32.f32 %0, %1;" : "=r"(u) : "f"(f));
    return __uint_as_float(u);
}
__device__ __forceinline__ uint32_t rna_u(uint32_t u) {
    uint32_t o;
    asm("cvt.rna.tf32.f32 %0, %1;" : "=r"(o) : "f"(__uint_as_float(u)));
    return o;
}

__device__ __forceinline__ void cp16(uint32_t dst, const void* src) {
    asm volatile("cp.async.cg.shared.global [%0], [%1], 16;"
        :: "r"(dst), "l"(src) : "memory");
}
#define CP_COMMIT() asm volatile("cp.async.commit_group;" ::: "memory")
#define CP_WAIT(N)  asm volatile("cp.async.wait_group %0;" :: "n"(N) : "memory")

// pack two fp32 into bf16x2 (hi) and residual bf16x2 (lo)
__device__ __forceinline__ void split_pack(float p0, float p1,
                                           uint32_t& hi2, uint32_t& lo2) {
    __nv_bfloat162 h = __floats2bfloat162_rn(p0, p1);
    float r0 = p0 - __bfloat162float(h.x);
    float r1 = p1 - __bfloat162float(h.y);
    __nv_bfloat162 l = __floats2bfloat162_rn(r0, r1);
    hi2 = *(uint32_t*)&h;
    lo2 = *(uint32_t*)&l;
}

// 128B-row swizzle (SW128)
#define SWZ128(off) ((off) ^ (((off) >> 3) & 0x70))

// ---------------------------------------------------------------------------
// tf32 single-pass mma.sync GEMM: C[M,N] = A[M,K] * B[N,K]^T.
// Inputs are RAW fp32; tf32 rounding (cvt.rna) applied in-register post-ldsm.
// CTA tile 128x128, K-chunk 32 fp32 (=128B rows, SW128), 4 warps (2m x 2n)
// of 64x64, 3-stage cp.async ring.
// mode 0: QKV -> Q/K as rna fp32 planes (Q scaled 0.125), V as bf16 hi/lo.
// mode 1: plain fp32 store to Cplain.
// ---------------------------------------------------------------------------
#define KC    32
#define TIL32 (128*128)               // 16384 bytes per fp32 tile
#define STG32 (2*TIL32)               // 32768 per stage (A,B)
#define GEMM_SMEM (3*STG32)           // 98304

__global__ void __launch_bounds__(128, 2) mma_gemm_kernel(
    const float* __restrict__ A32, const float* __restrict__ B32,
    float* __restrict__ Cplain, int mode)
{
    extern __shared__ char smc[];
    const uint32_t sb = smem_to_u32(smc);
    const int tid  = threadIdx.x;
    const int wid  = tid >> 5;
    const int lane = tid & 31;
    const int warp_m = (wid & 1) * 64;
    const int warp_n = (wid >> 1) * 64;
    const int row0 = blockIdx.y * 128;
    const int col0 = blockIdx.x * 128;

    float C[4][8][4];
    #pragma unroll
    for (int mi = 0; mi < 4; mi++)
        #pragma unroll
        for (int nf = 0; nf < 8; nf++)
            #pragma unroll
            for (int e = 0; e < 4; e++) C[mi][nf][e] = 0.f;

    const int NCH = E_ / KC;   // 32

    auto issue = [&](int c, int st) {
        const int k0 = c * KC;
        const uint32_t base = sb + st * STG32;
        #pragma unroll
        for (int l = 0; l < 8; l++) {
            int idx = l * 128 + tid;
            int r = idx >> 3, slot = idx & 7;
            uint32_t so = (uint32_t)SWZ128(r * 128 + slot * 16);
            cp16(base + so,         A32 + (size_t)(row0 + r) * E_ + k0 + slot * 4);
            cp16(base + TIL32 + so, B32 + (size_t)(col0 + r) * E_ + k0 + slot * 4);
        }
    };

    issue(0, 0); CP_COMMIT();
    issue(1, 1); CP_COMMIT();

    #pragma unroll 1
    for (int c = 0; c < NCH; c++) {
        CP_WAIT(1);
        __syncthreads();

        if (c + 2 < NCH) issue(c + 2, (c + 2) % 3);
        CP_COMMIT();

        const uint32_t bA = sb + (c % 3) * STG32;
        const uint32_t bB = bA + TIL32;

        #pragma unroll
        for (int ki = 0; ki < 4; ki++) {
            const int acolb = ki * 32 + (lane >> 4) * 16;
            uint32_t a[4][4];
            #pragma unroll
            for (int mi = 0; mi < 4; mi++) {
                uint32_t ao = (uint32_t)SWZ128(
                    (warp_m + mi * 16 + (lane & 15)) * 128 + acolb);
                ldsm_x4(a[mi][0], a[mi][1], a[mi][2], a[mi][3], bA + ao);
                a[mi][0] = rna_u(a[mi][0]); a[mi][1] = rna_u(a[mi][1]);
                a[mi][2] = rna_u(a[mi][2]); a[mi][3] = rna_u(a[mi][3]);
            }
            const int brow_off = ((lane >> 4) & 1) * 8 + (lane & 7);
            const int bcolb    = ki * 32 + ((lane >> 3) & 1) * 16;
            #pragma unroll
            for (int njp = 0; njp < 4; njp++) {
                uint32_t bo = (uint32_t)SWZ128(
                    (warp_n + njp * 16 + brow_off) * 128 + bcolb);
                uint32_t b0, b1, b2, b3;
                ldsm_x4(b0, b1, b2, b3, bB + bo);
                b0 = rna_u(b0); b1 = rna_u(b1);
                b2 = rna_u(b2); b3 = rna_u(b3);
                #pragma unroll
                for (int mi = 0; mi < 4; mi++) {
                    mma_tf32(C[mi][njp * 2],     a[mi][0], a[mi][1], a[mi][2], a[mi][3], b0, b1);
                    mma_tf32(C[mi][njp * 2 + 1], a[mi][0], a[mi][1], a[mi][2], a[mi][3], b2, b3);
                }
            }
        }
    }

    if (mode == 0) {
        #pragma unroll
        for (int mi = 0; mi < 4; mi++) {
            #pragma unroll
            for (int half = 0; half < 2; half++) {
                int t = row0 + warp_m + mi * 16 + (lane >> 2) + half * 8;
                int bb = t >> 11;
                int ss = t & (S_ - 1);
                #pragma unroll
                for (int nf = 0; nf < 8; nf++) {
                    int f = col0 + warp_n + nf * 8 + (lane & 3) * 2;
                    int which = f >> 10;
                    int rem = f & 1023;
                    int h = rem >> 6;
                    int d = rem & 63;
                    float v0 = C[mi][nf][half * 2];
                    float v1 = C[mi][nf][half * 2 + 1];
                    size_t idx = (((size_t)(bb * H_ + h)) * S_ + ss) * D_ + d;
                    if (which == 0) {
                        float2 v = make_float2(rna_tf32(v0 * 0.125f),
                                               rna_tf32(v1 * 0.125f));
                        *(float2*)(g_q32 + idx) = v;
                    } else if (which == 1) {
                        float2 v = make_float2(rna_tf32(v0), rna_tf32(v1));
                        *(float2*)(g_k32 + idx) = v;
                    } else {
                        uint32_t hi2, lo2;
                        split_pack(v0, v1, hi2, lo2);
                        *(uint32_t*)(g_vhi + idx) = hi2;
                        *(uint32_t*)(g_vlo + idx) = lo2;
                    }
                }
            }
        }
    } else {
        #pragma unroll
        for (int mi = 0; mi < 4; mi++) {
            #pragma unroll
            for (int half = 0; half < 2; half++) {
                int r = row0 + warp_m + mi * 16 + (lane >> 2) + half * 8;
                #pragma unroll
                for (int nf = 0; nf < 8; nf++) {
                    int f = col0 + warp_n + nf * 8 + (lane & 3) * 2;
                    float2 v = make_float2(C[mi][nf][half * 2],
                                           C[mi][nf][half * 2 + 1]);
                    *(float2*)(Cplain + (size_t)r * E_ + f) = v;
                }
            }
        }
    }
}

// ---------------------------------------------------------------------------
// Flash attention (causal): QK^T in single-pass tf32 (Q/K pre-rounded fp32
// planes), PV in bf16 hi/lo 3-pass. CTA: 64 q-rows, 4 warps, kv blocks of 64,
// 3-stage cp.async ring.
// SMEM: Q 2 fp32 planes [64][32] (16KB) + 3 stages x (K 2 planes fp32 +
//       Vhi + Vlo bf16) = 112KB.
// ---------------------------------------------------------------------------
#define APL   8192                    // one 64x128B plane
#define KVST  (4*APL)                 // K0,K1,Vhi,Vlo per stage = 32768
#define ATTN_SMEM (2*APL + 3*KVST)    // 114688 (112KB)

__global__ void __launch_bounds__(128, 2) attn_mma_kernel()
{
    extern __shared__ char sma[];
    const uint32_t sb = smem_to_u32(sma);
    const uint32_t oKV = 2 * APL;

    const int qb = (int)gridDim.x - 1 - (int)blockIdx.x;  // longest-first
    const int bh = blockIdx.y;
    const int bb = bh >> 4;
    const int hh = bh & 15;
    const int tid  = threadIdx.x;
    const int wid  = tid >> 5;
    const int lane = tid & 31;
    const int warp_m = wid * 16;

    const float* Kg = g_k32 + (size_t)bh * S_ * D_;
    const __nv_bfloat16* Vhb = g_vhi + (size_t)bh * S_ * D_;
    const __nv_bfloat16* Vlb = g_vlo + (size_t)bh * S_ * D_;

    auto issue_kv = [&](int kb, int st) {
        const uint32_t sbase = sb + oKV + st * KVST;
        // K: 64 rows x 64 fp32 -> 2 planes of [64][32] fp32 (128B rows)
        #pragma unroll
        for (int l = 0; l < 8; l++) {
            int idx = l * 128 + tid;
            int r = idx >> 4, sl = idx & 15;
            uint32_t so = (uint32_t)SWZ128(r * 128 + (sl & 7) * 16);
            cp16(sbase + (uint32_t)(sl >> 3) * APL + so,
                 Kg + (size_t)(kb * 64 + r) * D_ + sl * 4);
        }
        // V: bf16 hi/lo planes [64][64] (128B rows)
        #pragma unroll
        for (int l = 0; l < 4; l++) {
            int idx = l * 128 + tid;
            int r = idx >> 3, slot = idx & 7;
            uint32_t so = (uint32_t)SWZ128(r * 128 + slot * 16);
            size_t go = (size_t)(kb * 64 + r) * D_ + slot * 8;
            cp16(sbase + 2*APL + so, Vhb + go);
            cp16(sbase + 3*APL + so, Vlb + go);
        }
    };

    issue_kv(0, 0); CP_COMMIT();
    if (qb >= 1) issue_kv(1, 1);
    CP_COMMIT();

    // ---- load Q tile (fp32, 2 planes), swizzled ----
    {
        const float* Qg = g_q32 + ((size_t)bh * S_ + qb * 64) * D_;
        #pragma unroll
        for (int l = 0; l < 8; l++) {
            int idx = l * 128 + tid;
            int r = idx >> 4, sl = idx & 15;
            uint32_t so = (uint32_t)SWZ128(r * 128 + (sl & 7) * 16);
            *(float4*)(sma + (sl >> 3) * APL + so) =
                *(const float4*)(Qg + r * D_ + sl * 4);
        }
    }
    __syncthreads();

    // ---- preload Q fragments (8 k8-steps, tf32 m16k8) ----
    uint32_t aq[8][4];
    #pragma unroll
    for (int ki = 0; ki < 8; ki++) {
        int row = warp_m + (lane & 15);
        int colb = (ki & 3) * 32 + (lane >> 4) * 16;
        uint32_t ao = (uint32_t)SWZ128(row * 128 + colb);
        ldsm_x4(aq[ki][0], aq[ki][1], aq[ki][2], aq[ki][3],
                sb + (uint32_t)(ki >> 2) * APL + ao);
    }

    float m[2]  = {-1e30f, -1e30f};
    float lsum[2] = {0.f, 0.f};
    float o[8][4];
    #pragma unroll
    for (int nf = 0; nf < 8; nf++)
        #pragma unroll
        for (int e = 0; e < 4; e++) o[nf][e] = 0.f;

    #pragma unroll 1
    for (int kb = 0; kb <= qb; kb++) {
        CP_WAIT(1);
        __syncthreads();

        if (kb + 2 <= qb) issue_kv(kb + 2, (kb + 2) % 3);
        CP_COMMIT();

        const uint32_t stb = sb + oKV + (kb % 3) * KVST;
        const uint32_t bVhi = stb + 2*APL, bVlo = stb + 3*APL;

        // ---- scores S = Q . K^T (single-pass tf32) ----
        float s[8][4];
        #pragma unroll
        for (int nf = 0; nf < 8; nf++)
            #pragma unroll
            for (int e = 0; e < 4; e++) s[nf][e] = 0.f;

        #pragma unroll
        for (int ki = 0; ki < 8; ki++) {
            const uint32_t kplane = stb + (uint32_t)(ki >> 2) * APL;
            const int colb = (ki & 3) * 32 + ((lane >> 3) & 1) * 16;
            const int brow_off = ((lane >> 4) & 1) * 8 + (lane & 7);
            uint32_t kf[4][4];
            #pragma unroll
            for (int njp = 0; njp < 4; njp++) {
                uint32_t bo = (uint32_t)SWZ128(
                    (njp * 16 + brow_off) * 128 + colb);
                ldsm_x4(kf[njp][0], kf[njp][1], kf[njp][2], kf[njp][3],
                        kplane + bo);
            }
            #pragma unroll
            for (int njp = 0; njp < 4; njp++) {
                mma_tf32(s[njp * 2],     aq[ki][0], aq[ki][1], aq[ki][2], aq[ki][3],
                         kf[njp][0], kf[njp][1]);
                mma_tf32(s[njp * 2 + 1], aq[ki][0], aq[ki][1], aq[ki][2], aq[ki][3],
                         kf[njp][2], kf[njp][3]);
            }
        }

        if (kb == qb) {
            const int qrow0 = qb * 64 + warp_m + (lane >> 2);
            #pragma unroll
            for (int nf = 0; nf < 8; nf++) {
                int kcol = kb * 64 + nf * 8 + (lane & 3) * 2;
                #pragma unroll
                for (int e = 0; e < 4; e++) {
                    int q = qrow0 + (e >> 1) * 8;
                    int kv = kcol + (e & 1);
                    if (kv > q) s[nf][e] = -1e30f;
                }
            }
        }

        #pragma unroll
        for (int h = 0; h < 2; h++) {
            float rmax = -1e30f;
            #pragma unroll
            for (int nf = 0; nf < 8; nf++) {
                rmax = fmaxf(rmax, s[nf][2*h]);
                rmax = fmaxf(rmax, s[nf][2*h+1]);
            }
            rmax = fmaxf(rmax, __shfl_xor_sync(0xffffffffu, rmax, 1));
            rmax = fmaxf(rmax, __shfl_xor_sync(0xffffffffu, rmax, 2));

            float mnew = fmaxf(m[h], rmax);
            float corr = __expf(m[h] - mnew);
            m[h] = mnew;

            float rsum = 0.f;
            #pragma unroll
            for (int nf = 0; nf < 8; nf++) {
                float p0 = __expf(s[nf][2*h]   - mnew);
                float p1 = __expf(s[nf][2*h+1] - mnew);
                s[nf][2*h]   = p0;
                s[nf][2*h+1] = p1;
                rsum += p0 + p1;
            }
            rsum += __shfl_xor_sync(0xffffffffu, rsum, 1);
            rsum += __shfl_xor_sync(0xffffffffu, rsum, 2);
            lsum[h] = lsum[h] * corr + rsum;

            #pragma unroll
            for (int nf = 0; nf < 8; nf++) {
                o[nf][2*h]   *= corr;
                o[nf][2*h+1] *= corr;
            }
        }

        // ---- O += P . V (bf16 3-pass, P from regs, V trans ldsm) ----
        #pragma unroll
        for (int ki = 0; ki < 4; ki++) {
            uint32_t aph[4], apl[4];
            split_pack(s[2*ki][0],   s[2*ki][1],   aph[0], apl[0]);
            split_pack(s[2*ki][2],   s[2*ki][3],   aph[1], apl[1]);
            split_pack(s[2*ki+1][0], s[2*ki+1][1], aph[2], apl[2]);
            split_pack(s[2*ki+1][2], s[2*ki+1][3], aph[3], apl[3]);

            const int rowv = ki * 16 + (lane & 7) + ((lane >> 3) & 1) * 8;
            const int cb0  = ((lane >> 4) & 1) * 16;
            uint32_t vh[4][4], vl[4][4];
            #pragma unroll
            for (int nj = 0; nj < 4; nj++) {
                uint32_t ad = (uint32_t)SWZ128(rowv * 128 + cb0 + nj * 32);
                ldsm_x4_trans(vh[nj][0], vh[nj][1], vh[nj][2], vh[nj][3], bVhi + ad);
                ldsm_x4_trans(vl[nj][0], vl[nj][1], vl[nj][2], vl[nj][3], bVlo + ad);
            }
            #pragma unroll
            for (int nj = 0; nj < 4; nj++) {
                mma_bf16(o[nj * 2],     aph[0], aph[1], aph[2], aph[3], vh[nj][0], vh[nj][1]);
                mma_bf16(o[nj * 2 + 1], aph[0], aph[1], aph[2], aph[3], vh[nj][2], vh[nj][3]);
            }
            #pragma unroll
            for (int nj = 0; nj < 4; nj++) {
                mma_bf16(o[nj * 2],     apl[0], apl[1], apl[2], apl[3], vh[nj][0], vh[nj][1]);
                mma_bf16(o[nj * 2 + 1], apl[0], apl[1], apl[2], apl[3], vh[nj][2], vh[nj][3]);
            }
            #pragma unroll
            for (int nj = 0; nj < 4; nj++) {
                mma_bf16(o[nj * 2],     aph[0], aph[1], aph[2], aph[3], vl[nj][0], vl[nj][1]);
                mma_bf16(o[nj * 2 + 1], aph[0], aph[1], aph[2], aph[3], vl[nj][2], vl[nj][3]);
            }
        }
    }

    // ---- epilogue: O / l, plain fp32 to g_o [B,S,E] ----
    #pragma unroll
    for (int h = 0; h < 2; h++) {
        float inv = 1.0f / lsum[h];
        int r = warp_m + (lane >> 2) + h * 8;
        size_t t = (size_t)(bb * S_ + qb * 64 + r);
        #pragma unroll
        for (int nf = 0; nf < 8; nf++) {
            int dcol = hh * 64 + nf * 8 + (lane & 3) * 2;
            float2 v = make_float2(o[nf][2*h] * inv, o[nf][2*h+1] * inv);
            *(float2*)(g_o + t * E_ + dcol) = v;
        }
    }
}

// ---------------------------------------------------------------------------
extern "C" void kernel_launch(void* const* d_in, const int* in_sizes, int n_in,
                              void* d_out, int out_size)
{
    const float* x     = (const float*)d_in[0];   // [B,S,E]
    const float* w_qkv = (const float*)d_in[1];   // [3E,E]
    const float* w_out = (const float*)d_in[2];   // [E,E]
    float* out = (float*)d_out;                   // [B,S,E]

    float* og;
    cudaGetSymbolAddress((void**)&og, g_o);

    static bool attr_set = false;
    if (!attr_set) {
        cudaFuncSetAttribute(mma_gemm_kernel,
                             cudaFuncAttributeMaxDynamicSharedMemorySize,
                             GEMM_SMEM);
        cudaFuncSetAttribute(attn_mma_kernel,
                             cudaFuncAttributeMaxDynamicSharedMemorySize,
                             ATTN_SMEM);
        attr_set = true;
    }

    // 1) QKV projection (tf32, raw inputs, in-register rounding)
    {
        dim3 grid(F3 / 128, NT / 128);   // (24, 32)
        mma_gemm_kernel<<<grid, 128, GEMM_SMEM>>>(x, w_qkv, nullptr, 0);
    }

    // 2) Flash attention (causal): QK tf32 + PV bf16 -> fp32 O
    {
        dim3 grid(S_ / 64, B_ * H_);     // (32, 32)
        attn_mma_kernel<<<grid, 128, ATTN_SMEM>>>();
    }

    // 3) Output projection (tf32, raw inputs, in-register rounding)
    {
        dim3 grid(E_ / 128, NT / 128);   // (8, 32)
        mma_gemm_kernel<<<grid, 128, GEMM_SMEM>>>(og, w_out, out, 1);
    }
}